// round 1
// baseline (speedup 1.0000x reference)
#include <cuda_runtime.h>
#include <math.h>

// Problem constants
#define M_ROWS   16384      // B*S = 8*2048
#define E_DIM    768
#define NQ       8
#define FFN_DIM  3072
#define LN_EPS   1e-5f

// ---------------------------------------------------------------------------
// Scratch (device globals: no cudaMalloc allowed)
// ---------------------------------------------------------------------------
__device__ float g_z [M_ROWS * E_DIM];     // x + attn_out + bc   (pre-LN1)
__device__ float g_x1[M_ROWS * E_DIM];     // LN1 output
__device__ float g_q [M_ROWS * NQ];        // cos(x1[:, :8]) * cos(ry)
__device__ float g_h [M_ROWS * FFN_DIM];   // relu(q@W1 + b1)
__device__ float g_f [M_ROWS * E_DIM];     // x1 + ffn_out + b2   (pre-LN2)

// ---------------------------------------------------------------------------
// GEMM: C = op(A) @ B + bias + res
//   A: M x K row-major  (if APPLY_COS: element a -> cosf(a + rx[k % 64]))
//   B: K x N row-major
//   bias: N, res: M x N
// Tiles: 128x128x8, 256 threads, 8x8 per-thread microtile.
// Requires M%128==0, N%128==0, K%8==0 (true for all uses here).
// ---------------------------------------------------------------------------
template <bool APPLY_COS>
__global__ void __launch_bounds__(256)
gemm128_kernel(const float* __restrict__ A, const float* __restrict__ B,
               const float* __restrict__ bias, const float* __restrict__ res,
               const float* __restrict__ rx, float* __restrict__ C,
               int M, int N, int K)
{
    __shared__ float As[8][128];   // k-major (transposed on store)
    __shared__ float Bs[8][128];

    const int tid = threadIdx.x;
    const int tx  = tid & 15;          // 0..15 -> 8 cols each
    const int ty  = tid >> 4;          // 0..15 -> 8 rows each
    const int row0 = blockIdx.y * 128;
    const int col0 = blockIdx.x * 128;

    // A-tile loader: thread -> (row ar, k-offset ac), one float4
    const int ar = tid >> 1;           // 0..127
    const int ac = (tid & 1) * 4;      // 0 or 4
    // B-tile loader: thread -> (k-row br, col bc), one float4
    const int br = tid >> 5;           // 0..7
    const int bc = (tid & 31) * 4;     // 0..124

    const float* Aptr = A + (size_t)(row0 + ar) * K + ac;
    const float* Bptr = B + (size_t)br * N + (col0 + bc);

    float acc[8][8];
    #pragma unroll
    for (int i = 0; i < 8; i++)
        #pragma unroll
        for (int j = 0; j < 8; j++) acc[i][j] = 0.f;

    for (int k0 = 0; k0 < K; k0 += 8) {
        float4 av = *(const float4*)(Aptr + k0);
        if (APPLY_COS) {
            const int kb = (k0 + ac) & 63;     // channel % 64 (K=768, 64-aligned tiles)
            av.x = cosf(av.x + rx[kb + 0]);
            av.y = cosf(av.y + rx[kb + 1]);
            av.z = cosf(av.z + rx[kb + 2]);
            av.w = cosf(av.w + rx[kb + 3]);
        }
        As[ac + 0][ar] = av.x;
        As[ac + 1][ar] = av.y;
        As[ac + 2][ar] = av.z;
        As[ac + 3][ar] = av.w;

        *(float4*)&Bs[br][bc] = *(const float4*)(Bptr + (size_t)k0 * N);
        __syncthreads();

        #pragma unroll
        for (int kk = 0; kk < 8; kk++) {
            float4 a0 = *(const float4*)&As[kk][ty * 8];
            float4 a1 = *(const float4*)&As[kk][ty * 8 + 4];
            float4 b0 = *(const float4*)&Bs[kk][tx * 8];
            float4 b1 = *(const float4*)&Bs[kk][tx * 8 + 4];
            float a[8] = {a0.x, a0.y, a0.z, a0.w, a1.x, a1.y, a1.z, a1.w};
            float b[8] = {b0.x, b0.y, b0.z, b0.w, b1.x, b1.y, b1.z, b1.w};
            #pragma unroll
            for (int i = 0; i < 8; i++)
                #pragma unroll
                for (int j = 0; j < 8; j++)
                    acc[i][j] = fmaf(a[i], b[j], acc[i][j]);
        }
        __syncthreads();
    }

    // Epilogue: + bias + residual
    #pragma unroll
    for (int i = 0; i < 8; i++) {
        const int r = row0 + ty * 8 + i;
        #pragma unroll
        for (int j = 0; j < 8; j += 4) {
            const int c = col0 + tx * 8 + j;
            const size_t idx = (size_t)r * N + c;
            float4 rv = *(const float4*)(res + idx);
            float4 bv = *(const float4*)(bias + c);
            float4 o;
            o.x = acc[i][j + 0] + bv.x + rv.x;
            o.y = acc[i][j + 1] + bv.y + rv.y;
            o.z = acc[i][j + 2] + bv.z + rv.z;
            o.w = acc[i][j + 3] + bv.w + rv.w;
            *(float4*)(C + idx) = o;
        }
    }
}

// ---------------------------------------------------------------------------
// Row LayerNorm over E=768 (one block per row, 256 threads, 3 elems/thread)
// If WRITE_Q: q[m, i] = cos(out[m, i]) * cos(ry[i]) for i < 8
// ---------------------------------------------------------------------------
template <bool WRITE_Q>
__global__ void __launch_bounds__(256)
ln_kernel(const float* __restrict__ in, const float* __restrict__ g,
          const float* __restrict__ b, const float* __restrict__ ry,
          float* __restrict__ out, float* __restrict__ q)
{
    const int m   = blockIdx.x;
    const int tid = threadIdx.x;
    const float* row = in + (size_t)m * E_DIM;

    float v[3];
    float s = 0.f, ss = 0.f;
    #pragma unroll
    for (int j = 0; j < 3; j++) {
        v[j] = row[tid + j * 256];
        s  += v[j];
        ss += v[j] * v[j];
    }

    // warp reduce
    #pragma unroll
    for (int o = 16; o > 0; o >>= 1) {
        s  += __shfl_xor_sync(0xffffffffu, s,  o);
        ss += __shfl_xor_sync(0xffffffffu, ss, o);
    }
    __shared__ float red[16];
    const int warp = tid >> 5, lane = tid & 31;
    if (lane == 0) { red[warp] = s; red[warp + 8] = ss; }
    __syncthreads();
    if (tid == 0) {
        float S = 0.f, SS = 0.f;
        #pragma unroll
        for (int w = 0; w < 8; w++) { S += red[w]; SS += red[w + 8]; }
        red[0] = S; red[8] = SS;
    }
    __syncthreads();

    const float mu  = red[0] * (1.f / E_DIM);
    const float var = red[8] * (1.f / E_DIM) - mu * mu;
    const float inv = rsqrtf(var + LN_EPS);

    #pragma unroll
    for (int j = 0; j < 3; j++) {
        const int e = tid + j * 256;
        const float y = (v[j] - mu) * inv * g[e] + b[e];
        out[(size_t)m * E_DIM + e] = y;
        if (WRITE_Q && j == 0 && tid < NQ)
            q[(size_t)m * NQ + tid] = cosf(y) * cosf(ry[tid]);
    }
}

// ---------------------------------------------------------------------------
// FFN first layer: h[m, j] = relu(sum_i q[m, i] * W1[i, j] + b1[j])
// One block per row; 256 threads, 3 float4 each (3072 cols).
// ---------------------------------------------------------------------------
__global__ void __launch_bounds__(256)
ffn1_kernel(const float* __restrict__ q, const float* __restrict__ W1,
            const float* __restrict__ b1, float* __restrict__ h)
{
    const int m = blockIdx.x;
    __shared__ float qs[NQ];
    if (threadIdx.x < NQ) qs[threadIdx.x] = q[(size_t)m * NQ + threadIdx.x];
    __syncthreads();

    float qr[NQ];
    #pragma unroll
    for (int i = 0; i < NQ; i++) qr[i] = qs[i];

    #pragma unroll
    for (int blk = 0; blk < 3; blk++) {
        const int j = blk * 1024 + threadIdx.x * 4;
        float4 acc = *(const float4*)(b1 + j);
        #pragma unroll
        for (int i = 0; i < NQ; i++) {
            const float4 w = *(const float4*)(W1 + (size_t)i * FFN_DIM + j);
            acc.x = fmaf(qr[i], w.x, acc.x);
            acc.y = fmaf(qr[i], w.y, acc.y);
            acc.z = fmaf(qr[i], w.z, acc.z);
            acc.w = fmaf(qr[i], w.w, acc.w);
        }
        acc.x = fmaxf(acc.x, 0.f);
        acc.y = fmaxf(acc.y, 0.f);
        acc.z = fmaxf(acc.z, 0.f);
        acc.w = fmaxf(acc.w, 0.f);
        *(float4*)(h + (size_t)m * FFN_DIM + j) = acc;
    }
}

// ---------------------------------------------------------------------------
// Launch
// ---------------------------------------------------------------------------
extern "C" void kernel_launch(void* const* d_in, const int* in_sizes, int n_in,
                              void* d_out, int out_size)
{
    const float* x   = (const float*)d_in[0];
    const float* rx  = (const float*)d_in[1];
    const float* ry  = (const float*)d_in[2];
    const float* Wc  = (const float*)d_in[3];
    const float* bc  = (const float*)d_in[4];
    const float* W1  = (const float*)d_in[5];
    const float* b1  = (const float*)d_in[6];
    const float* W2  = (const float*)d_in[7];
    const float* b2  = (const float*)d_in[8];
    const float* g1  = (const float*)d_in[9];
    const float* be1 = (const float*)d_in[10];
    const float* g2  = (const float*)d_in[11];
    const float* be2 = (const float*)d_in[12];
    float* out = (float*)d_out;

    float *z, *x1, *q, *h, *f;
    cudaGetSymbolAddress((void**)&z,  g_z);
    cudaGetSymbolAddress((void**)&x1, g_x1);
    cudaGetSymbolAddress((void**)&q,  g_q);
    cudaGetSymbolAddress((void**)&h,  g_h);
    cudaGetSymbolAddress((void**)&f,  g_f);

    // 1) attn: z = cos(x + rx) @ Wc + bc + x
    gemm128_kernel<true><<<dim3(E_DIM / 128, M_ROWS / 128), 256>>>(
        x, Wc, bc, x, rx, z, M_ROWS, E_DIM, E_DIM);

    // 2) x1 = LN(z; g1, be1); q = cos(x1[:, :8]) * cos(ry)
    ln_kernel<true><<<M_ROWS, 256>>>(z, g1, be1, ry, x1, q);

    // 3) h = relu(q @ W1 + b1)
    ffn1_kernel<<<M_ROWS, 256>>>(q, W1, b1, h);

    // 4) f = h @ W2 + b2 + x1
    gemm128_kernel<false><<<dim3(E_DIM / 128, M_ROWS / 128), 256>>>(
        h, W2, b2, x1, nullptr, f, M_ROWS, E_DIM, FFN_DIM);

    // 5) out = LN(f; g2, be2)
    ln_kernel<false><<<M_ROWS, 256>>>(f, g2, be2, nullptr, out, nullptr);
}

// round 3
// speedup vs baseline: 3.7621x; 3.7621x over previous
#include <cuda_runtime.h>
#include <math.h>
#include <stdint.h>

// Problem constants
#define M_ROWS   16384      // B*S
#define E_DIM    768
#define NQ       8
#define FFN_DIM  3072
#define LN_EPS   1e-5f

// ---------------------------------------------------------------------------
// Scratch (device globals: no cudaMalloc allowed)
// ---------------------------------------------------------------------------
__device__ float g_cx [M_ROWS * E_DIM];     // cos(x + rx), tf32-rounded
__device__ float g_z  [M_ROWS * E_DIM];     // pre-LN1
__device__ float g_x1 [M_ROWS * E_DIM];     // LN1 output (full fp32)
__device__ float g_q  [M_ROWS * NQ];
__device__ float g_h  [M_ROWS * FFN_DIM];   // relu(q@W1+b1), tf32-rounded
__device__ float g_f  [M_ROWS * E_DIM];     // pre-LN2
__device__ float g_WcT[E_DIM * E_DIM];      // Wc^T, tf32-rounded
__device__ float g_W2T[E_DIM * FFN_DIM];    // W2^T, tf32-rounded

// ---------------------------------------------------------------------------
// Helpers (all baseline PTX, no sm_103a-only features)
// ---------------------------------------------------------------------------
__device__ __forceinline__ uint32_t smem_u32(const void* p) {
    uint32_t a;
    asm("{ .reg .u64 t; cvta.to.shared.u64 t, %1; cvt.u32.u64 %0, t; }"
        : "=r"(a) : "l"(p));
    return a;
}

__device__ __forceinline__ float to_tf32(float x) {
    uint32_t r;
    asm("cvt.rna.tf32.f32 %0, %1;" : "=r"(r) : "f"(x));
    return __uint_as_float(r);
}

__device__ __forceinline__ void cp16(uint32_t s, const void* g) {
    asm volatile("cp.async.ca.shared.global [%0], [%1], 16;" :: "r"(s), "l"(g));
}
#define CP_COMMIT() asm volatile("cp.async.commit_group;" ::: "memory")
#define CP_WAIT(n)  asm volatile("cp.async.wait_group %0;" :: "n"(n) : "memory")

__device__ __forceinline__ void mma8(float* c,
                                     uint32_t a0, uint32_t a1, uint32_t a2, uint32_t a3,
                                     uint32_t b0, uint32_t b1) {
    asm volatile(
        "mma.sync.aligned.m16n8k8.row.col.f32.tf32.tf32.f32 "
        "{%0,%1,%2,%3}, {%4,%5,%6,%7}, {%8,%9}, {%0,%1,%2,%3};"
        : "+f"(c[0]), "+f"(c[1]), "+f"(c[2]), "+f"(c[3])
        : "r"(a0), "r"(a1), "r"(a2), "r"(a3), "r"(b0), "r"(b1));
}

// ---------------------------------------------------------------------------
// Tensor-core GEMM (mma.sync tf32):
//   C[M, 768] = A[M, K] @ Bt[768, K]^T + bias + res
//   A row-major (tf32-rounded), Bt row-major N x K (tf32-rounded)
// CTA: 128 threads (4 warps), tile 128(M) x 128(N), warp tile 64x64.
// K_TILE=32, cp.async double buffer. Smem tiles row-major, stride 36 floats.
// ---------------------------------------------------------------------------
#define KT        32
#define TS        36                    // smem row stride (floats)
#define HALF_FL   (128 * TS)            // one matrix tile (floats)
#define STAGE_FL  (2 * HALF_FL)         // A + B
#define SMEM_FL   (2 * STAGE_FL)        // double buffer
#define SMEM_BYTES (SMEM_FL * 4)

__global__ void __launch_bounds__(128, 2)
gemm_mma_kernel(const float* __restrict__ A, const float* __restrict__ Bt,
                const float* __restrict__ bias, const float* __restrict__ res,
                float* __restrict__ C, int K, int NK)
{
    extern __shared__ float smem[];
    const uint32_t sbase = smem_u32(smem);

    const int tid  = threadIdx.x;
    const int w    = tid >> 5, lane = tid & 31;
    const int g    = lane >> 2, tg = lane & 3;
    const int row0 = blockIdx.y * 128;
    const int col0 = blockIdx.x * 128;
    const int wm   = (w >> 1) * 64;
    const int wn   = (w & 1) * 64;

    // copy mapping: 128 rows x 8 float4; thread covers rows (tid>>3)+16p, col4 tid&7
    const int crow = tid >> 3;
    const int ccol = tid & 7;
    const float* Agb = A  + (size_t)row0 * K + ccol * 4;
    const float* Bgb = Bt + (size_t)col0 * K + ccol * 4;

    float acc[4][8][4];
    #pragma unroll
    for (int i = 0; i < 4; i++)
        #pragma unroll
        for (int j = 0; j < 8; j++)
            #pragma unroll
            for (int v = 0; v < 4; v++) acc[i][j][v] = 0.f;

    // issue one K-tile's cp.asyncs into stage s
    auto issue = [&](int kt, int s) {
        const int k0 = kt * KT;
        const uint32_t sA = sbase + (uint32_t)(s * STAGE_FL) * 4u;
        const uint32_t sB = sA + (uint32_t)HALF_FL * 4u;
        #pragma unroll
        for (int p = 0; p < 8; p++) {
            const int r = crow + 16 * p;
            const uint32_t so = (uint32_t)(r * TS + ccol * 4) * 4u;
            cp16(sA + so, Agb + (size_t)r * K + k0);
            cp16(sB + so, Bgb + (size_t)r * K + k0);
        }
        CP_COMMIT();
    };

    issue(0, 0);
    if (NK > 1) issue(1, 1);

    for (int kt = 0; kt < NK; kt++) {
        const int s = kt & 1;
        if (kt < NK - 1) { CP_WAIT(1); } else { CP_WAIT(0); }
        __syncthreads();

        const float* As = smem + s * STAGE_FL;
        const float* Bs = As + HALF_FL;
        const float* Aw = As + (wm + g) * TS + tg;
        const float* Bw = Bs + (wn + g) * TS + tg;

        #pragma unroll
        for (int kk = 0; kk < KT; kk += 8) {
            uint32_t a[4][4];
            #pragma unroll
            for (int i = 0; i < 4; i++) {
                a[i][0] = __float_as_uint(Aw[(16 * i    ) * TS + kk    ]);
                a[i][1] = __float_as_uint(Aw[(16 * i + 8) * TS + kk    ]);
                a[i][2] = __float_as_uint(Aw[(16 * i    ) * TS + kk + 4]);
                a[i][3] = __float_as_uint(Aw[(16 * i + 8) * TS + kk + 4]);
            }
            uint32_t b[8][2];
            #pragma unroll
            for (int j = 0; j < 8; j++) {
                b[j][0] = __float_as_uint(Bw[(8 * j) * TS + kk    ]);
                b[j][1] = __float_as_uint(Bw[(8 * j) * TS + kk + 4]);
            }
            #pragma unroll
            for (int i = 0; i < 4; i++)
                #pragma unroll
                for (int j = 0; j < 8; j++)
                    mma8(acc[i][j], a[i][0], a[i][1], a[i][2], a[i][3],
                         b[j][0], b[j][1]);
        }
        __syncthreads();
        if (kt + 2 < NK) issue(kt + 2, s);
    }

    // Epilogue: + bias + res, write C. Cols even -> float2 aligned.
    float2 bj[8];
    #pragma unroll
    for (int j = 0; j < 8; j++)
        bj[j] = *(const float2*)(bias + col0 + wn + 8 * j + 2 * tg);

    #pragma unroll
    for (int i = 0; i < 4; i++) {
        const int r0 = row0 + wm + 16 * i + g;
        const int r1 = r0 + 8;
        #pragma unroll
        for (int j = 0; j < 8; j++) {
            const int c = col0 + wn + 8 * j + 2 * tg;
            const size_t i0 = (size_t)r0 * E_DIM + c;
            const size_t i1 = (size_t)r1 * E_DIM + c;
            float2 rv0 = *(const float2*)(res + i0);
            float2 rv1 = *(const float2*)(res + i1);
            float2 o0, o1;
            o0.x = acc[i][j][0] + bj[j].x + rv0.x;
            o0.y = acc[i][j][1] + bj[j].y + rv0.y;
            o1.x = acc[i][j][2] + bj[j].x + rv1.x;
            o1.y = acc[i][j][3] + bj[j].y + rv1.y;
            *(float2*)(C + i0) = o0;
            *(float2*)(C + i1) = o1;
        }
    }
}

// ---------------------------------------------------------------------------
// cos(x + rx) precompute, tf32-rounded output
// ---------------------------------------------------------------------------
__global__ void __launch_bounds__(256)
cosx_kernel(const float* __restrict__ x, const float* __restrict__ rx,
            float* __restrict__ cx)
{
    const int i = blockIdx.x * 256 + threadIdx.x;       // float4 index
    float4 v = ((const float4*)x)[i];
    const int e = (i * 4) & 63;
    v.x = to_tf32(cosf(v.x + rx[e + 0]));
    v.y = to_tf32(cosf(v.y + rx[e + 1]));
    v.z = to_tf32(cosf(v.z + rx[e + 2]));
    v.w = to_tf32(cosf(v.w + rx[e + 3]));
    ((float4*)cx)[i] = v;
}

// ---------------------------------------------------------------------------
// Transpose: in R x C -> out C x R, tf32-rounded output
// ---------------------------------------------------------------------------
__global__ void __launch_bounds__(256)
transpose_kernel(const float* __restrict__ in, float* __restrict__ out, int R, int C)
{
    __shared__ float t[32][33];
    const int c0 = blockIdx.x * 32, r0 = blockIdx.y * 32;
    #pragma unroll
    for (int j = 0; j < 4; j++)
        t[threadIdx.y + j * 8][threadIdx.x] =
            in[(size_t)(r0 + threadIdx.y + j * 8) * C + (c0 + threadIdx.x)];
    __syncthreads();
    #pragma unroll
    for (int j = 0; j < 4; j++)
        out[(size_t)(c0 + threadIdx.y + j * 8) * R + (r0 + threadIdx.x)] =
            to_tf32(t[threadIdx.x][threadIdx.y + j * 8]);
}

// ---------------------------------------------------------------------------
// Row LayerNorm over E=768 (one block per row); optionally writes q
// ---------------------------------------------------------------------------
template <bool WRITE_Q>
__global__ void __launch_bounds__(256)
ln_kernel(const float* __restrict__ in, const float* __restrict__ g,
          const float* __restrict__ b, const float* __restrict__ ry,
          float* __restrict__ out, float* __restrict__ q)
{
    const int m   = blockIdx.x;
    const int tid = threadIdx.x;
    const float* row = in + (size_t)m * E_DIM;

    float v[3];
    float s = 0.f, ss = 0.f;
    #pragma unroll
    for (int j = 0; j < 3; j++) {
        v[j] = row[tid + j * 256];
        s  += v[j];
        ss += v[j] * v[j];
    }
    #pragma unroll
    for (int o = 16; o > 0; o >>= 1) {
        s  += __shfl_xor_sync(0xffffffffu, s,  o);
        ss += __shfl_xor_sync(0xffffffffu, ss, o);
    }
    __shared__ float red[16];
    const int warp = tid >> 5, lane = tid & 31;
    if (lane == 0) { red[warp] = s; red[warp + 8] = ss; }
    __syncthreads();
    if (tid == 0) {
        float S = 0.f, SS = 0.f;
        #pragma unroll
        for (int w = 0; w < 8; w++) { S += red[w]; SS += red[w + 8]; }
        red[0] = S; red[8] = SS;
    }
    __syncthreads();

    const float mu  = red[0] * (1.f / E_DIM);
    const float var = red[8] * (1.f / E_DIM) - mu * mu;
    const float inv = rsqrtf(var + LN_EPS);

    #pragma unroll
    for (int j = 0; j < 3; j++) {
        const int e = tid + j * 256;
        const float y = (v[j] - mu) * inv * g[e] + b[e];
        out[(size_t)m * E_DIM + e] = y;
        if (WRITE_Q && j == 0 && tid < NQ)
            q[(size_t)m * NQ + tid] = cosf(y) * cosf(ry[tid]);
    }
}

// ---------------------------------------------------------------------------
// FFN first layer: h = relu(q @ W1 + b1), K=8 — bandwidth-bound
// Output tf32-rounded (feeds the tensor-core GEMM as A).
// ---------------------------------------------------------------------------
__global__ void __launch_bounds__(256)
ffn1_kernel(const float* __restrict__ q, const float* __restrict__ W1,
            const float* __restrict__ b1, float* __restrict__ h)
{
    const int m = blockIdx.x;
    __shared__ float qs[NQ];
    if (threadIdx.x < NQ) qs[threadIdx.x] = q[(size_t)m * NQ + threadIdx.x];
    __syncthreads();
    float qr[NQ];
    #pragma unroll
    for (int i = 0; i < NQ; i++) qr[i] = qs[i];

    #pragma unroll
    for (int blk = 0; blk < 3; blk++) {
        const int j = blk * 1024 + threadIdx.x * 4;
        float4 acc = *(const float4*)(b1 + j);
        #pragma unroll
        for (int i = 0; i < NQ; i++) {
            const float4 w = *(const float4*)(W1 + (size_t)i * FFN_DIM + j);
            acc.x = fmaf(qr[i], w.x, acc.x);
            acc.y = fmaf(qr[i], w.y, acc.y);
            acc.z = fmaf(qr[i], w.z, acc.z);
            acc.w = fmaf(qr[i], w.w, acc.w);
        }
        acc.x = to_tf32(fmaxf(acc.x, 0.f));
        acc.y = to_tf32(fmaxf(acc.y, 0.f));
        acc.z = to_tf32(fmaxf(acc.z, 0.f));
        acc.w = to_tf32(fmaxf(acc.w, 0.f));
        *(float4*)(h + (size_t)m * FFN_DIM + j) = acc;
    }
}

// ---------------------------------------------------------------------------
// Launch
// ---------------------------------------------------------------------------
extern "C" void kernel_launch(void* const* d_in, const int* in_sizes, int n_in,
                              void* d_out, int out_size)
{
    const float* x   = (const float*)d_in[0];
    const float* rx  = (const float*)d_in[1];
    const float* ry  = (const float*)d_in[2];
    const float* Wc  = (const float*)d_in[3];
    const float* bc  = (const float*)d_in[4];
    const float* W1  = (const float*)d_in[5];
    const float* b1  = (const float*)d_in[6];
    const float* W2  = (const float*)d_in[7];
    const float* b2  = (const float*)d_in[8];
    const float* g1  = (const float*)d_in[9];
    const float* be1 = (const float*)d_in[10];
    const float* g2  = (const float*)d_in[11];
    const float* be2 = (const float*)d_in[12];
    float* out = (float*)d_out;

    float *cx, *z, *x1, *q, *h, *f, *WcT, *W2T;
    cudaGetSymbolAddress((void**)&cx,  g_cx);
    cudaGetSymbolAddress((void**)&z,   g_z);
    cudaGetSymbolAddress((void**)&x1,  g_x1);
    cudaGetSymbolAddress((void**)&q,   g_q);
    cudaGetSymbolAddress((void**)&h,   g_h);
    cudaGetSymbolAddress((void**)&f,   g_f);
    cudaGetSymbolAddress((void**)&WcT, g_WcT);
    cudaGetSymbolAddress((void**)&W2T, g_W2T);

    cudaFuncSetAttribute(gemm_mma_kernel,
                         cudaFuncAttributeMaxDynamicSharedMemorySize, SMEM_BYTES);

    // 0) weight transposes (tf32) + cos precompute (tf32)
    transpose_kernel<<<dim3(E_DIM / 32, E_DIM / 32), dim3(32, 8)>>>(Wc, WcT, E_DIM, E_DIM);
    transpose_kernel<<<dim3(E_DIM / 32, FFN_DIM / 32), dim3(32, 8)>>>(W2, W2T, FFN_DIM, E_DIM);
    cosx_kernel<<<(M_ROWS * E_DIM / 4) / 256, 256>>>(x, rx, cx);

    // 1) z = cos(x+rx) @ Wc + bc + x        (tf32 mma.sync)
    gemm_mma_kernel<<<dim3(E_DIM / 128, M_ROWS / 128), 128, SMEM_BYTES>>>(
        cx, WcT, bc, x, z, E_DIM, E_DIM / KT);

    // 2) x1 = LN(z); q = cos(x1[:, :8]) * cos(ry)
    ln_kernel<true><<<M_ROWS, 256>>>(z, g1, be1, ry, x1, q);

    // 3) h = relu(q @ W1 + b1)
    ffn1_kernel<<<M_ROWS, 256>>>(q, W1, b1, h);

    // 4) f = h @ W2 + b2 + x1               (tf32 mma.sync)
    gemm_mma_kernel<<<dim3(E_DIM / 128, M_ROWS / 128), 128, SMEM_BYTES>>>(
        h, W2T, b2, x1, f, FFN_DIM, FFN_DIM / KT);

    // 5) out = LN(f)
    ln_kernel<false><<<M_ROWS, 256>>>(f, g2, be2, nullptr, out, nullptr);
}